// round 16
// baseline (speedup 1.0000x reference)
#include <cuda_runtime.h>
#include <cuda_fp16.h>
#include <cstdint>
#include <math.h>

#define NH    16
#define DH    64
#define LSEQ  2048
#define NB    2
#define INNER 1024
#define QK_SCALE 0.125f

// Scratch (__device__ globals; allocation-free rule) — fp32 proven pipeline.
__device__ float g_q[(size_t)NB*NH*LSEQ*DH];   // [b,h,l,dh]
__device__ float g_k[(size_t)NB*NH*LSEQ*DH];
__device__ float g_v[(size_t)NB*NH*LSEQ*DH];
__device__ float g_z[(size_t)NB*LSEQ*INNER];   // [b,l,h*dh]

// ---------------------------------------------------------------------------
// Helpers (sm_80-baseline; safe on plain sm_103 target). NO cp.async.
// ---------------------------------------------------------------------------
__device__ __forceinline__ void mma16(float d[4], const uint32_t a[4],
                                      const uint32_t b[2]) {
    asm volatile(
        "mma.sync.aligned.m16n8k16.row.col.f32.f16.f16.f32 "
        "{%0,%1,%2,%3}, {%4,%5,%6,%7}, {%8,%9}, {%0,%1,%2,%3};"
        : "+f"(d[0]), "+f"(d[1]), "+f"(d[2]), "+f"(d[3])
        : "r"(a[0]), "r"(a[1]), "r"(a[2]), "r"(a[3]),
          "r"(b[0]), "r"(b[1]));
}
__device__ __forceinline__ uint32_t pack2(float lo, float hi) {
    __half2 h = __floats2half2_rn(lo, hi);
    return *(uint32_t*)&h;
}

// ---------------------------------------------------------------------------
// fp16 GEMM, warp M-tile = 32 rows (VERBATIM round 15 — measured 171us).
// C[4096][Ncols] = A[4096][1024] @ W[1024][Ncols] (W native layout).
// Block 128m x 64n, 128 threads = 4 warps; K-tile 64 (16 iterations).
// mode 0: scatter C to q/k/v (fp32). mode 1: C + bias -> out.
// ---------------------------------------------------------------------------
__global__ __launch_bounds__(128) void gemm_w32(const float* __restrict__ A,
                                                const float* __restrict__ W,
                                                const float* __restrict__ bias,
                                                float* __restrict__ outp,
                                                int Ncols, int mode)
{
    extern __shared__ uint32_t sh[];
    uint32_t* As2 = sh;              // [128 m][36] u32 (32 kpairs + pad)
    uint32_t* Bs2 = sh + 128 * 36;   // [32 kpair][68] u32 (64 n + pad)

    const int tid  = threadIdx.x;
    const int lane = tid & 31;
    const int w    = tid >> 5;      // 0..3
    const int g    = lane >> 2;
    const int t    = lane & 3;
    const int m0   = blockIdx.y * 128;
    const int n0   = blockIdx.x * 64;
    const int rw   = w * 32;        // warp's 32-row slab

    float acc[2][8][4];
    #pragma unroll
    for (int s = 0; s < 2; s++)
        #pragma unroll
        for (int j = 0; j < 8; j++)
            #pragma unroll
            for (int r = 0; r < 4; r++) acc[s][j][r] = 0.f;

    #pragma unroll 1
    for (int kt = 0; kt < 16; kt++) {
        __syncthreads();
        // Stage A 128x64 (fp32 -> half2 pairs along k): 2048 float4
        #pragma unroll
        for (int i = 0; i < 16; i++) {
            int idx = tid + 128 * i;
            int r = idx >> 4, c = (idx & 15) * 4;
            float4 a4 = *(const float4*)&A[(size_t)(m0 + r) * 1024 + kt * 64 + c];
            uint2 p = { pack2(a4.x, a4.y), pack2(a4.z, a4.w) };
            *(uint2*)&As2[r * 36 + (c >> 1)] = p;
        }
        // Stage B 64x64: pack k-rows 2kp,2kp+1 into half2: 512 uint4
        #pragma unroll
        for (int i = 0; i < 4; i++) {
            int idx = tid + 128 * i;
            int kp = idx >> 4, nc = (idx & 15) * 4;
            const float* wr = W + (size_t)(kt * 64 + 2 * kp) * Ncols + n0 + nc;
            float4 e = *(const float4*)wr;
            float4 o = *(const float4*)(wr + Ncols);
            uint4 p = { pack2(e.x, o.x), pack2(e.y, o.y),
                        pack2(e.z, o.z), pack2(e.w, o.w) };
            *(uint4*)&Bs2[kp * 68 + nc] = p;
        }
        __syncthreads();

        #pragma unroll
        for (int ks = 0; ks < 4; ks++) {
            uint32_t af[2][4];
            #pragma unroll
            for (int s = 0; s < 2; s++) {
                int row = rw + s * 16;
                af[s][0] = As2[(row + g) * 36 + ks * 8 + t];
                af[s][1] = As2[(row + g + 8) * 36 + ks * 8 + t];
                af[s][2] = As2[(row + g) * 36 + ks * 8 + t + 4];
                af[s][3] = As2[(row + g + 8) * 36 + ks * 8 + t + 4];
            }
            #pragma unroll
            for (int j = 0; j < 8; j++) {
                uint32_t bf[2];
                bf[0] = Bs2[(ks * 8 + t) * 68 + j * 8 + g];
                bf[1] = Bs2[(ks * 8 + t + 4) * 68 + j * 8 + g];
                mma16(acc[0][j], af[0], bf);
                mma16(acc[1][j], af[1], bf);
            }
        }
    }

    #pragma unroll
    for (int s = 0; s < 2; s++) {
        int r_lo = m0 + rw + s * 16 + g;
        int r_hi = r_lo + 8;
        #pragma unroll
        for (int j = 0; j < 8; j++) {
            int n = n0 + j * 8 + 2 * t;
            if (mode == 1) {
                float2 o0 = { acc[s][j][0] + bias[n], acc[s][j][1] + bias[n + 1] };
                float2 o1 = { acc[s][j][2] + bias[n], acc[s][j][3] + bias[n + 1] };
                *(float2*)&outp[(size_t)r_lo * 1024 + n] = o0;
                *(float2*)&outp[(size_t)r_hi * 1024 + n] = o1;
            } else {
                int three = n >> 10, rem = n & 1023, hh = rem >> 6, dd = rem & 63;
                float* base = (three == 0) ? g_q : (three == 1) ? g_k : g_v;
                int bb_lo = r_lo >> 11, ll_lo = r_lo & 2047;
                int bb_hi = r_hi >> 11, ll_hi = r_hi & 2047;
                float2 o0 = { acc[s][j][0], acc[s][j][1] };
                float2 o1 = { acc[s][j][2], acc[s][j][3] };
                *(float2*)&base[(((size_t)(bb_lo * NH + hh) * LSEQ) + ll_lo) * DH + dd] = o0;
                *(float2*)&base[(((size_t)(bb_hi * NH + hh) * LSEQ) + ll_hi) * DH + dd] = o1;
            }
        }
    }
}

// ---------------------------------------------------------------------------
// Attention (VERBATIM round 14 — part of the 2120us best):
// BM=128 (8 warps, 256 threads), warp tile 16 q-rows,
// mask via direct LDG at fragment coords, no-max exact softmax.
// ---------------------------------------------------------------------------
__global__ __launch_bounds__(256) void attn_mma(const float* __restrict__ mask,
                                                float* __restrict__ z)
{
    extern __shared__ uint32_t sh[];
    uint32_t* Ks2 = sh;                      // [64 seq][36] half2 along dh
    uint32_t* Vs2 = Ks2 + 64 * 36;           // [32 seqpair][68] half2 = seq pair
    uint32_t* Ps2 = Vs2 + 32 * 68;           // [128 q][36] half2 along seq

    const int tid  = threadIdx.x;
    const int lane = tid & 31;
    const int w    = tid >> 5;               // 0..7
    const int g    = lane >> 2;
    const int t    = lane & 3;
    const int qb   = blockIdx.x;
    const int bh   = blockIdx.y;
    const int bb   = bh >> 4, hh = bh & 15;
    const int q0   = qb * 128;
    const int rw   = w * 16;

    const float* qp = g_q + ((size_t)bh * LSEQ + q0) * DH;
    const float* kp = g_k + (size_t)bh * LSEQ * DH;
    const float* vp = g_v + (size_t)bh * LSEQ * DH;
    const float* mrow_lo = mask + ((size_t)bb * LSEQ + q0 + rw + g) * LSEQ;
    const float* mrow_hi = mrow_lo + (size_t)8 * LSEQ;

    // Q fragments direct from fp32 gmem, scale folded
    uint32_t qa[4][4];
    #pragma unroll
    for (int ks = 0; ks < 4; ks++) {
        const float* q_lo = qp + (rw + g) * 64 + ks * 16 + 2 * t;
        const float* q_hi = q_lo + 8 * 64;
        float2 a = *(const float2*)q_lo;
        float2 b = *(const float2*)q_hi;
        float2 c = *(const float2*)(q_lo + 8);
        float2 d = *(const float2*)(q_hi + 8);
        qa[ks][0] = pack2(QK_SCALE * a.x, QK_SCALE * a.y);
        qa[ks][1] = pack2(QK_SCALE * b.x, QK_SCALE * b.y);
        qa[ks][2] = pack2(QK_SCALE * c.x, QK_SCALE * c.y);
        qa[ks][3] = pack2(QK_SCALE * d.x, QK_SCALE * d.y);
    }

    float zacc[8][4];
    #pragma unroll
    for (int j = 0; j < 8; j++)
        #pragma unroll
        for (int r = 0; r < 4; r++) zacc[j][r] = 0.f;
    float sa_lo = 0.f, sa_hi = 0.f, sk_lo = 0.f, sk_hi = 0.f;

    #pragma unroll 1
    for (int jt = 0; jt < LSEQ / 64; jt++) {
        __syncthreads();   // all warps done reading Ks2/Vs2 from prior iter
        // Stage K 64x64 (fp32 -> half2 along dh): 1024 float4, 256 threads
        #pragma unroll
        for (int i = 0; i < 4; i++) {
            int idx = tid + 256 * i;
            int r = idx >> 4, c = (idx & 15) * 4;
            float4 k4 = *(const float4*)&kp[(size_t)(jt * 64 + r) * 64 + c];
            uint2 p = { pack2(k4.x, k4.y), pack2(k4.z, k4.w) };
            *(uint2*)&Ks2[r * 36 + (c >> 1)] = p;
        }
        // Stage V 64x64: pack seq rows 2s,2s+1 into half2: 512 entries
        #pragma unroll
        for (int i = 0; i < 2; i++) {
            int idx = tid + 256 * i;
            int s = idx >> 4, d = (idx & 15) * 4;
            const float* vr = vp + (size_t)(jt * 64 + 2 * s) * 64 + d;
            float4 e = *(const float4*)vr;
            float4 o = *(const float4*)(vr + 64);
            uint4 p = { pack2(e.x, o.x), pack2(e.y, o.y),
                        pack2(e.z, o.z), pack2(e.w, o.w) };
            *(uint4*)&Vs2[s * 68 + d] = p;
        }
        __syncthreads();

        // S = Q K^T (scaled)
        float sacc[8][4];
        #pragma unroll
        for (int j = 0; j < 8; j++)
            #pragma unroll
            for (int r = 0; r < 4; r++) sacc[j][r] = 0.f;
        #pragma unroll
        for (int ks = 0; ks < 4; ks++) {
            #pragma unroll
            for (int j = 0; j < 8; j++) {
                uint32_t bf[2];
                bf[0] = Ks2[(j * 8 + g) * 36 + ks * 8 + t];
                bf[1] = Ks2[(j * 8 + g) * 36 + ks * 8 + t + 4];
                mma16(sacc[j], qa[ks], bf);
            }
        }

        // exp + mask (direct LDG at fragment coords) + row sums; write P
        #pragma unroll
        for (int j = 0; j < 8; j++) {
            float p0 = __expf(sacc[j][0]);
            float p1 = __expf(sacc[j][1]);
            float p2 = __expf(sacc[j][2]);
            float p3 = __expf(sacc[j][3]);
            float2 mlo = *(const float2*)&mrow_lo[jt * 64 + j * 8 + 2 * t];
            float2 mhi = *(const float2*)&mrow_hi[jt * 64 + j * 8 + 2 * t];
            float w0 = p0 * mlo.x, w1 = p1 * mlo.y;
            float w2 = p2 * mhi.x, w3 = p3 * mhi.y;
            sa_lo += p0 + p1;  sa_hi += p2 + p3;
            sk_lo += w0 + w1;  sk_hi += w2 + w3;
            Ps2[(rw + g) * 36 + j * 4 + t]     = pack2(w0, w1);
            Ps2[(rw + g + 8) * 36 + j * 4 + t] = pack2(w2, w3);
        }
        __syncwarp();   // P rows are warp-private

        // zacc += P @ V
        #pragma unroll
        for (int ks = 0; ks < 4; ks++) {
            uint32_t pa4[4];
            pa4[0] = Ps2[(rw + g) * 36 + ks * 8 + t];
            pa4[1] = Ps2[(rw + g + 8) * 36 + ks * 8 + t];
            pa4[2] = Ps2[(rw + g) * 36 + ks * 8 + t + 4];
            pa4[3] = Ps2[(rw + g + 8) * 36 + ks * 8 + t + 4];
            #pragma unroll
            for (int j = 0; j < 8; j++) {
                uint32_t bf[2];
                bf[0] = Vs2[(ks * 8 + t) * 68 + j * 8 + g];
                bf[1] = Vs2[(ks * 8 + t + 4) * 68 + j * 8 + g];
                mma16(zacc[j], pa4, bf);
            }
        }
    }

    #pragma unroll
    for (int d = 1; d <= 2; d <<= 1) {
        sa_lo += __shfl_xor_sync(0xffffffffu, sa_lo, d);
        sa_hi += __shfl_xor_sync(0xffffffffu, sa_hi, d);
        sk_lo += __shfl_xor_sync(0xffffffffu, sk_lo, d);
        sk_hi += __shfl_xor_sync(0xffffffffu, sk_hi, d);
    }
    float inv_lo = 1.f / (sk_lo + 1e-10f * sa_lo);
    float inv_hi = 1.f / (sk_hi + 1e-10f * sa_hi);

    size_t row_lo = (size_t)bb * LSEQ + q0 + rw + g;
    size_t row_hi = row_lo + 8;
    #pragma unroll
    for (int j = 0; j < 8; j++) {
        int dh = hh * 64 + j * 8 + 2 * t;
        float2 o0 = { zacc[j][0] * inv_lo, zacc[j][1] * inv_lo };
        float2 o1 = { zacc[j][2] * inv_hi, zacc[j][3] * inv_hi };
        *(float2*)&z[row_lo * INNER + dh] = o0;
        *(float2*)&z[row_hi * INNER + dh] = o1;
    }
}

// ---------------------------------------------------------------------------
extern "C" void kernel_launch(void* const* d_in, const int* in_sizes, int n_in,
                              void* d_out, int out_size)
{
    const float* x     = (const float*)d_in[0];  // [2,2048,1024]
    const float* mask  = (const float*)d_in[1];  // [2,2048,2048]
    const float* W_qkv = (const float*)d_in[2];  // [1024,3072]
    const float* W_out = (const float*)d_in[3];  // [1024,1024]
    const float* b_out = (const float*)d_in[4];  // [1024]
    float* out = (float*)d_out;

    const int gemm_smem = (128 * 36 + 32 * 68) * 4;   // 27136 B
    cudaFuncSetAttribute(gemm_w32, cudaFuncAttributeMaxDynamicSharedMemorySize, gemm_smem);

    // QKV projection -> fp32 q/k/v (W in native [k][n] layout)
    gemm_w32<<<dim3(3072 / 64, 4096 / 128), 128, gemm_smem>>>(
        x, W_qkv, nullptr, nullptr, 3072, 0);

    // Attention (round-14 proven: BM=128, 256 threads, warp=16 rows)
    const int attn_smem = (64 * 36 + 32 * 68 + 128 * 36) * 4;  // 36352 B
    cudaFuncSetAttribute(attn_mma, cudaFuncAttributeMaxDynamicSharedMemorySize, attn_smem);
    attn_mma<<<dim3(LSEQ / 128, NB * NH), 256, attn_smem>>>(mask, g_z);

    // Output projection + bias
    gemm_w32<<<dim3(1024 / 64, 4096 / 128), 128, gemm_smem>>>(
        g_z, W_out, b_out, out, 1024, 1);
}

// round 17
// speedup vs baseline: 1.0817x; 1.0817x over previous
#include <cuda_runtime.h>
#include <cuda_fp16.h>
#include <cstdint>
#include <math.h>

#define NH    16
#define DH    64
#define LSEQ  2048
#define NB    2
#define INNER 1024
#define QK_SCALE 0.125f

// Scratch (__device__ globals; allocation-free rule) — fp32 proven pipeline.
__device__ float g_q[(size_t)NB*NH*LSEQ*DH];   // [b,h,l,dh]
__device__ float g_k[(size_t)NB*NH*LSEQ*DH];
__device__ float g_v[(size_t)NB*NH*LSEQ*DH];
__device__ float g_z[(size_t)NB*LSEQ*INNER];   // [b,l,h*dh]

// ---------------------------------------------------------------------------
// Helpers (sm_80-baseline; safe on plain sm_103 target). NO cp.async.
// ---------------------------------------------------------------------------
__device__ __forceinline__ void mma16(float d[4], const uint32_t a[4],
                                      const uint32_t b[2]) {
    asm volatile(
        "mma.sync.aligned.m16n8k16.row.col.f32.f16.f16.f32 "
        "{%0,%1,%2,%3}, {%4,%5,%6,%7}, {%8,%9}, {%0,%1,%2,%3};"
        : "+f"(d[0]), "+f"(d[1]), "+f"(d[2]), "+f"(d[3])
        : "r"(a[0]), "r"(a[1]), "r"(a[2]), "r"(a[3]),
          "r"(b[0]), "r"(b[1]));
}
__device__ __forceinline__ uint32_t pack2(float lo, float hi) {
    __half2 h = __floats2half2_rn(lo, hi);
    return *(uint32_t*)&h;
}

// ---------------------------------------------------------------------------
// fp16 mma GEMM (VERBATIM round 14 — part of the 2120us best pairing).
// C[4096][Ncols] = A[4096][1024] @ W[1024][Ncols] (W native layout).
// 128 threads = 4 warps; block tile 64x64; K-tile 128.
// mode 0: scatter C to q/k/v (fp32). mode 1: C + bias -> out.
// ---------------------------------------------------------------------------
__global__ __launch_bounds__(128) void gemm64h(const float* __restrict__ A,
                                               const float* __restrict__ W,
                                               const float* __restrict__ bias,
                                               float* __restrict__ outp,
                                               int Ncols, int mode)
{
    extern __shared__ uint32_t sh[];
    uint32_t* As2 = sh;              // [64][68] u32 (half2 pairs along k)
    uint32_t* Bs2 = sh + 64 * 68;    // [64][68] u32 (half2 = two k-rows)

    const int tid  = threadIdx.x;
    const int lane = tid & 31;
    const int w    = tid >> 5;
    const int g    = lane >> 2;
    const int t    = lane & 3;
    const int m0   = blockIdx.y * 64;
    const int n0   = blockIdx.x * 64;
    const int rw   = w * 16;

    float acc[8][4];
    #pragma unroll
    for (int j = 0; j < 8; j++)
        #pragma unroll
        for (int r = 0; r < 4; r++) acc[j][r] = 0.f;

    #pragma unroll 1
    for (int kt = 0; kt < 8; kt++) {
        __syncthreads();
        // Stage A 64x128 (fp32 -> half2 pairs along k)
        #pragma unroll
        for (int i = 0; i < 16; i++) {
            int idx = tid + 128 * i;
            int r = idx >> 5, c = (idx & 31) * 4;
            float4 a4 = *(const float4*)&A[(size_t)(m0 + r) * 1024 + kt * 128 + c];
            uint2 p = { pack2(a4.x, a4.y), pack2(a4.z, a4.w) };
            *(uint2*)&As2[r * 68 + (c >> 1)] = p;
        }
        // Stage B 128x64: pack rows 2k,2k+1 into half2
        #pragma unroll
        for (int i = 0; i < 8; i++) {
            int idx = tid + 128 * i;
            int kp = idx >> 4, nc = (idx & 15) * 4;
            const float* wr = W + (size_t)(kt * 128 + 2 * kp) * Ncols + n0 + nc;
            float4 e = *(const float4*)wr;
            float4 o = *(const float4*)(wr + Ncols);
            uint4 p = { pack2(e.x, o.x), pack2(e.y, o.y),
                        pack2(e.z, o.z), pack2(e.w, o.w) };
            *(uint4*)&Bs2[kp * 68 + nc] = p;
        }
        __syncthreads();

        #pragma unroll
        for (int ks = 0; ks < 8; ks++) {
            uint32_t af[4];
            af[0] = As2[(rw + g) * 68 + ks * 8 + t];
            af[1] = As2[(rw + g + 8) * 68 + ks * 8 + t];
            af[2] = As2[(rw + g) * 68 + ks * 8 + t + 4];
            af[3] = As2[(rw + g + 8) * 68 + ks * 8 + t + 4];
            #pragma unroll
            for (int j = 0; j < 8; j++) {
                uint32_t bf[2];
                bf[0] = Bs2[(ks * 8 + t) * 68 + j * 8 + g];
                bf[1] = Bs2[(ks * 8 + t + 4) * 68 + j * 8 + g];
                mma16(acc[j], af, bf);
            }
        }
    }

    int r_lo = m0 + rw + g;
    int r_hi = r_lo + 8;
    #pragma unroll
    for (int j = 0; j < 8; j++) {
        int n = n0 + j * 8 + 2 * t;
        if (mode == 1) {
            float2 o0 = { acc[j][0] + bias[n], acc[j][1] + bias[n + 1] };
            float2 o1 = { acc[j][2] + bias[n], acc[j][3] + bias[n + 1] };
            *(float2*)&outp[(size_t)r_lo * 1024 + n] = o0;
            *(float2*)&outp[(size_t)r_hi * 1024 + n] = o1;
        } else {
            int three = n >> 10, rem = n & 1023, hh = rem >> 6, dd = rem & 63;
            float* base = (three == 0) ? g_q : (three == 1) ? g_k : g_v;
            int bb_lo = r_lo >> 11, ll_lo = r_lo & 2047;
            int bb_hi = r_hi >> 11, ll_hi = r_hi & 2047;
            float2 o0 = { acc[j][0], acc[j][1] };
            float2 o1 = { acc[j][2], acc[j][3] };
            *(float2*)&base[(((size_t)(bb_lo * NH + hh) * LSEQ) + ll_lo) * DH + dd] = o0;
            *(float2*)&base[(((size_t)(bb_hi * NH + hh) * LSEQ) + ll_hi) * DH + dd] = o1;
        }
    }
}

// ---------------------------------------------------------------------------
// Attention, register-lean variant for 2 blocks/SM:
//  - QK mma fused with exp per-j (sacc 32 -> 4 live regs)
//  - eps*Z term dropped (contributes ~2e-10 relative; mask rows never all-zero)
//  - __launch_bounds__(256, 2) pins regs <= 128 -> 16 warps/SM
// BM=128 (8 warps), warp tile 16 q-rows, mask via direct LDG.
// ---------------------------------------------------------------------------
__global__ __launch_bounds__(256, 2) void attn_mma(const float* __restrict__ mask,
                                                   float* __restrict__ z)
{
    extern __shared__ uint32_t sh[];
    uint32_t* Ks2 = sh;                      // [64 seq][36] half2 along dh
    uint32_t* Vs2 = Ks2 + 64 * 36;           // [32 seqpair][68] half2 = seq pair
    uint32_t* Ps2 = Vs2 + 32 * 68;           // [128 q][36] half2 along seq

    const int tid  = threadIdx.x;
    const int lane = tid & 31;
    const int w    = tid >> 5;               // 0..7
    const int g    = lane >> 2;
    const int t    = lane & 3;
    const int qb   = blockIdx.x;
    const int bh   = blockIdx.y;
    const int bb   = bh >> 4, hh = bh & 15;
    const int q0   = qb * 128;
    const int rw   = w * 16;

    const float* qp = g_q + ((size_t)bh * LSEQ + q0) * DH;
    const float* kp = g_k + (size_t)bh * LSEQ * DH;
    const float* vp = g_v + (size_t)bh * LSEQ * DH;
    const float* mrow_lo = mask + ((size_t)bb * LSEQ + q0 + rw + g) * LSEQ;
    const float* mrow_hi = mrow_lo + (size_t)8 * LSEQ;

    // Q fragments direct from fp32 gmem, scale folded
    uint32_t qa[4][4];
    #pragma unroll
    for (int ks = 0; ks < 4; ks++) {
        const float* q_lo = qp + (rw + g) * 64 + ks * 16 + 2 * t;
        const float* q_hi = q_lo + 8 * 64;
        float2 a = *(const float2*)q_lo;
        float2 b = *(const float2*)q_hi;
        float2 c = *(const float2*)(q_lo + 8);
        float2 d = *(const float2*)(q_hi + 8);
        qa[ks][0] = pack2(QK_SCALE * a.x, QK_SCALE * a.y);
        qa[ks][1] = pack2(QK_SCALE * b.x, QK_SCALE * b.y);
        qa[ks][2] = pack2(QK_SCALE * c.x, QK_SCALE * c.y);
        qa[ks][3] = pack2(QK_SCALE * d.x, QK_SCALE * d.y);
    }

    float zacc[8][4];
    #pragma unroll
    for (int j = 0; j < 8; j++)
        #pragma unroll
        for (int r = 0; r < 4; r++) zacc[j][r] = 0.f;
    float sk_lo = 0.f, sk_hi = 0.f;

    #pragma unroll 1
    for (int jt = 0; jt < LSEQ / 64; jt++) {
        __syncthreads();   // all warps done reading Ks2/Vs2 from prior iter
        // Stage K 64x64 (fp32 -> half2 along dh): 1024 float4, 256 threads
        #pragma unroll
        for (int i = 0; i < 4; i++) {
            int idx = tid + 256 * i;
            int r = idx >> 4, c = (idx & 15) * 4;
            float4 k4 = *(const float4*)&kp[(size_t)(jt * 64 + r) * 64 + c];
            uint2 p = { pack2(k4.x, k4.y), pack2(k4.z, k4.w) };
            *(uint2*)&Ks2[r * 36 + (c >> 1)] = p;
        }
        // Stage V 64x64: pack seq rows 2s,2s+1 into half2: 512 entries
        #pragma unroll
        for (int i = 0; i < 2; i++) {
            int idx = tid + 256 * i;
            int s = idx >> 4, d = (idx & 15) * 4;
            const float* vr = vp + (size_t)(jt * 64 + 2 * s) * 64 + d;
            float4 e = *(const float4*)vr;
            float4 o = *(const float4*)(vr + 64);
            uint4 p = { pack2(e.x, o.x), pack2(e.y, o.y),
                        pack2(e.z, o.z), pack2(e.w, o.w) };
            *(uint4*)&Vs2[s * 68 + d] = p;
        }
        __syncthreads();

        // Per-j: S fragment (4 dependent mma) then exp+mask+sum+store P.
        // Unrolled j gives ptxas independent chains to interleave while
        // keeping only ~2 sacc sets live (vs 32 regs before).
        #pragma unroll
        for (int j = 0; j < 8; j++) {
            float sacc[4] = {0.f, 0.f, 0.f, 0.f};
            #pragma unroll
            for (int ks = 0; ks < 4; ks++) {
                uint32_t bf[2];
                bf[0] = Ks2[(j * 8 + g) * 36 + ks * 8 + t];
                bf[1] = Ks2[(j * 8 + g) * 36 + ks * 8 + t + 4];
                mma16(sacc, qa[ks], bf);
            }
            float p0 = __expf(sacc[0]);
            float p1 = __expf(sacc[1]);
            float p2 = __expf(sacc[2]);
            float p3 = __expf(sacc[3]);
            float2 mlo = *(const float2*)&mrow_lo[jt * 64 + j * 8 + 2 * t];
            float2 mhi = *(const float2*)&mrow_hi[jt * 64 + j * 8 + 2 * t];
            float w0 = p0 * mlo.x, w1 = p1 * mlo.y;
            float w2 = p2 * mhi.x, w3 = p3 * mhi.y;
            sk_lo += w0 + w1;  sk_hi += w2 + w3;
            Ps2[(rw + g) * 36 + j * 4 + t]     = pack2(w0, w1);
            Ps2[(rw + g + 8) * 36 + j * 4 + t] = pack2(w2, w3);
        }
        __syncwarp();   // P rows are warp-private

        // zacc += P @ V
        #pragma unroll
        for (int ks = 0; ks < 4; ks++) {
            uint32_t pa4[4];
            pa4[0] = Ps2[(rw + g) * 36 + ks * 8 + t];
            pa4[1] = Ps2[(rw + g + 8) * 36 + ks * 8 + t];
            pa4[2] = Ps2[(rw + g) * 36 + ks * 8 + t + 4];
            pa4[3] = Ps2[(rw + g + 8) * 36 + ks * 8 + t + 4];
            #pragma unroll
            for (int j = 0; j < 8; j++) {
                uint32_t bf[2];
                bf[0] = Vs2[(ks * 8 + t) * 68 + j * 8 + g];
                bf[1] = Vs2[(ks * 8 + t + 4) * 68 + j * 8 + g];
                mma16(zacc[j], pa4, bf);
            }
        }
    }

    #pragma unroll
    for (int d = 1; d <= 2; d <<= 1) {
        sk_lo += __shfl_xor_sync(0xffffffffu, sk_lo, d);
        sk_hi += __shfl_xor_sync(0xffffffffu, sk_hi, d);
    }
    // eps*Z term dropped: contributes O(1e-10) relative; guard against 0/0.
    float inv_lo = 1.f / (sk_lo + 1e-20f);
    float inv_hi = 1.f / (sk_hi + 1e-20f);

    size_t row_lo = (size_t)bb * LSEQ + q0 + rw + g;
    size_t row_hi = row_lo + 8;
    #pragma unroll
    for (int j = 0; j < 8; j++) {
        int dh = hh * 64 + j * 8 + 2 * t;
        float2 o0 = { zacc[j][0] * inv_lo, zacc[j][1] * inv_lo };
        float2 o1 = { zacc[j][2] * inv_hi, zacc[j][3] * inv_hi };
        *(float2*)&z[row_lo * INNER + dh] = o0;
        *(float2*)&z[row_hi * INNER + dh] = o1;
    }
}

// ---------------------------------------------------------------------------
extern "C" void kernel_launch(void* const* d_in, const int* in_sizes, int n_in,
                              void* d_out, int out_size)
{
    const float* x     = (const float*)d_in[0];  // [2,2048,1024]
    const float* mask  = (const float*)d_in[1];  // [2,2048,2048]
    const float* W_qkv = (const float*)d_in[2];  // [1024,3072]
    const float* W_out = (const float*)d_in[3];  // [1024,1024]
    const float* b_out = (const float*)d_in[4];  // [1024]
    float* out = (float*)d_out;

    const int gemm_smem = (64 * 68 + 64 * 68) * 4;   // 34816 B
    cudaFuncSetAttribute(gemm64h, cudaFuncAttributeMaxDynamicSharedMemorySize, gemm_smem);

    // QKV projection -> fp32 q/k/v (W in native [k][n] layout)
    gemm64h<<<dim3(3072 / 64, 4096 / 64), 128, gemm_smem>>>(
        x, W_qkv, nullptr, nullptr, 3072, 0);

    // Attention (BM=128, 256 threads, 2 blocks/SM target)
    const int attn_smem = (64 * 36 + 32 * 68 + 128 * 36) * 4;  // 36352 B
    cudaFuncSetAttribute(attn_mma, cudaFuncAttributeMaxDynamicSharedMemorySize, attn_smem);
    attn_mma<<<dim3(LSEQ / 128, NB * NH), 256, attn_smem>>>(mask, g_z);

    // Output projection + bias
    gemm64h<<<dim3(1024 / 64, 4096 / 64), 128, gemm_smem>>>(
        g_z, W_out, b_out, out, 1024, 1);
}